// round 11
// baseline (speedup 1.0000x reference)
#include <cuda_runtime.h>

typedef unsigned long long ull;

#define B_   256
#define T_   1000
#define H_   512
#define NTN  16          // column tiles (32 cols each)
#define NTM  8           // batch tiles (32 batches each)
#define NCTA (NTN*NTM)   // 128
#define NTHR 512
#define KC   128         // K chunk staged in smem
#define NCH  (H_/KC)     // 4
#define HSS  132         // padded row stride (floats)

// shared memory layout (float offsets)
#define OFF_W4Z 0
#define OFF_W4R 16384
#define OFF_W4H 32768
#define OFF_HS  49152
#define HS_BUF  (32*HSS)                 // 4224 floats per buffer
#define OFF_C   (OFF_HS + 2*HS_BUF)      // 57600
#define SMEM_FLOATS (OFF_C + 352)        // 57952
#define SMEM_BYTES  (SMEM_FLOATS*4)      // 231808

// persistent device state
__device__ float g_hstate[B_*H_];        // compact h_t (L2-hot)
__device__ float g_hr[B_*H_];
__device__ float g_k[B_];
__device__ float g_kpart[NTN*B_];
__device__ unsigned g_cnt[NTM*32];

// ---- packed f32x2 helpers (Blackwell FFMA2 via PTX) ----
__device__ __forceinline__ ull fma2(ull a, ull b, ull c){ ull d; asm("fma.rn.f32x2 %0,%1,%2,%3;":"=l"(d):"l"(a),"l"(b),"l"(c)); return d; }
__device__ __forceinline__ void unpack2(ull v, float& lo, float& hi){ asm("mov.b64 {%0,%1},%2;":"=f"(lo),"=f"(hi):"l"(v)); }
__device__ __forceinline__ float hsum2(ull v){ float lo,hi; unpack2(v,lo,hi); return lo+hi; }

__device__ __forceinline__ float sigm(float x){ return 1.0f/(1.0f+__expf(-x)); }
__device__ __forceinline__ float tanh_(float x){ return 2.0f/(1.0f+__expf(-2.0f*x)) - 1.0f; }

// split group barrier on a monotonic counter (16 CTAs per group)
__device__ __forceinline__ void bar_arrive(unsigned* cnt){
    __syncthreads();
    if (threadIdx.x == 0){
        asm volatile("red.release.gpu.global.add.u32 [%0], 1;" :: "l"(cnt) : "memory");
    }
}
__device__ __forceinline__ void bar_wait(unsigned* cnt, unsigned target){
    if (threadIdx.x == 0){
        unsigned v;
        do { asm volatile("ld.acquire.gpu.global.u32 %0, [%1];" : "=r"(v) : "l"(cnt) : "memory"); } while (v < target);
    }
    __syncthreads();
}

__global__ void init_kernel(){
    int i = threadIdx.x;
    if (i < NTM*32) g_cnt[i] = 0u;
}

// MAC blocks: hreg = ulonglong2, .x = h pair (k0,k1), .y = (k2,k3)
#define P1B(hreg, wz0, wz1, wr0, wr1, AZ, AR) \
    AZ.x = fma2(hreg.x, wz0.x, AZ.x); AZ.y = fma2(hreg.x, wz0.y, AZ.y); \
    AR.x = fma2(hreg.x, wr0.x, AR.x); AR.y = fma2(hreg.x, wr0.y, AR.y); \
    AZ.x = fma2(hreg.y, wz1.x, AZ.x); AZ.y = fma2(hreg.y, wz1.y, AZ.y); \
    AR.x = fma2(hreg.y, wr1.x, AR.x); AR.y = fma2(hreg.y, wr1.y, AR.y);

#define P2B(hreg, w0, w1, AH) \
    AH.x = fma2(hreg.x, w0.x, AH.x); AH.y = fma2(hreg.x, w0.y, AH.y); \
    AH.x = fma2(hreg.y, w1.x, AH.x); AH.y = fma2(hreg.y, w1.y, AH.y);

__global__ void __launch_bounds__(NTHR, 1) mcgru_kernel(
    const float* __restrict__ inp, const float* __restrict__ St, const float* __restrict__ Mass,
    const float* __restrict__ Wz, const float* __restrict__ bz,
    const float* __restrict__ Wr, const float* __restrict__ br,
    const float* __restrict__ Wh, const float* __restrict__ bh,
    const float* __restrict__ Wk, const float* __restrict__ bk,
    float* __restrict__ out)
{
    extern __shared__ float sm[];
    float* hS0 = sm + OFF_HS;
    float* hS1 = sm + OFF_HS + HS_BUF;
    float* red = sm + OFF_HS;            // alias over both buffers
    float* cs  = sm + OFF_C;             // epilogue constants
    const ulonglong2* W4Zu = (const ulonglong2*)(sm + OFF_W4Z);
    const ulonglong2* W4Ru = (const ulonglong2*)(sm + OFF_W4R);
    const ulonglong2* W4Hu = (const ulonglong2*)(sm + OFF_W4H);

    const int tid   = threadIdx.x;
    const int tileN = blockIdx.x & (NTN-1);
    const int tileM = blockIdx.x >> 4;
    const int c0    = tileN * 32;
    const int kh    = tid >> 7;          // k-quarter 0..3
    const int r7    = tid & 127;
    const int p     = r7 & 15;           // col pair -> cols c0+2p, c0+2p+1
    const int bq    = r7 >> 4;           // 0..7 -> batches 4bq..4bq+3
    const int b0    = bq * 4;
    const int gbase = tileM*32 + b0;
    const int jp    = 2*p;
    const int cc    = c0 + jp;
    unsigned* cnt   = &g_cnt[tileM*32];

    // ---- prologue: interleaved weight layout in SMEM ----
    for (int i = tid; i < 4096; i += NTHR){
        int kq = i >> 4, pp = i & 15;
        int c = c0 + 2*pp;
        const float2 z0 = *(const float2*)&Wz[(2*kq+1)*H_ + c];
        const float2 z1 = *(const float2*)&Wz[(2*kq+2)*H_ + c];
        ((float4*)(sm + OFF_W4Z))[i] = make_float4(z0.x, z1.x, z0.y, z1.y);
        const float2 r0 = *(const float2*)&Wr[(2*kq+1)*H_ + c];
        const float2 r1 = *(const float2*)&Wr[(2*kq+2)*H_ + c];
        ((float4*)(sm + OFF_W4R))[i] = make_float4(r0.x, r1.x, r0.y, r1.y);
        const float2 h0 = *(const float2*)&Wh[(2*kq+1)*H_ + c];
        const float2 h1 = *(const float2*)&Wh[(2*kq+2)*H_ + c];
        ((float4*)(sm + OFF_W4H))[i] = make_float4(h0.x, h1.x, h0.y, h1.y);
    }
    if (tid < 32){
        cs[tid]       = Wz[c0 + tid];            // vz0
        cs[32 + tid]  = Wr[c0 + tid];            // vr0
        cs[64 + tid]  = Wh[c0 + tid];            // vh0
        cs[96 + tid]  = Wh[513*H_ + c0 + tid];   // v513
        cs[128 + tid] = Wh[514*H_ + c0 + tid];   // v514
        cs[160 + tid] = bz[c0 + tid];
        cs[192 + tid] = br[c0 + tid];
        cs[224 + tid] = bh[c0 + tid];
        cs[256 + tid] = Wk[c0 + tid];
        cs[288 + tid] = St[tileM*32 + tid];
        cs[320 + tid] = Mass[tileM*32 + tid];
    }
    const float wkH = __ldg(&Wk[H_]);
    const float bk0 = __ldg(&bk[0]);
    __syncthreads();

    // t-invariant staging addresses (2 float4 per thread per chunk)
    int srow[2], soff[2];
    #pragma unroll
    for (int u = 0; u < 2; u++){
        int i = tid + u*NTHR;
        srow[u] = i >> 5;
        soff[u] = (i & 31)*4;
    }
    const float* hsrc1[2];  // phase1 source: g_hstate (compact, L2-hot)
    const float* hsrc2[2];  // phase2 source: g_hr
    int sdst[2];
    #pragma unroll
    for (int u = 0; u < 2; u++){
        hsrc1[u] = g_hstate + (tileM*32 + srow[u])*H_ + soff[u];
        hsrc2[u] = g_hr     + (tileM*32 + srow[u])*H_ + soff[u];
        sdst[u]  = srow[u]*HSS + soff[u];
    }
    // running output pointers
    float* outp[4];
    const float* inpp[4];
    #pragma unroll
    for (int i = 0; i < 4; i++){
        outp[i] = out + (size_t)(gbase+i)*T_*H_ + cc;
        inpp[i] = inp + (size_t)(gbase+i)*T_;
    }

    float2 ho_[4], z_[4];
    #pragma unroll
    for (int i = 0; i < 4; i++) ho_[i] = make_float2(0.f, 0.f);

    float kreg = 0.0f;
    unsigned bar = 0;

    #pragma unroll 1
    for (int t = 0; t < T_; t++){
        // ---- k finalize from step t-1 partials (leader column-tile) ----
        if (tileN == 0 && tid < 32){
            int gb = tileM*32 + tid;
            if (t == 0){
                kreg = 0.0f;
            } else {
                float s = kreg * wkH + bk0;
                #pragma unroll
                for (int n = 0; n < NTN; n++) s += __ldcg(&g_kpart[n*B_ + gb]);
                kreg = sigm(s);
            }
            g_k[gb] = kreg;
        }

        float xb[4];
        if (kh == 0){
            #pragma unroll
            for (int i = 0; i < 4; i++) xb[i] = __ldg(inpp[i] + t);
        }

        // ---- phase 1: z, r = sigmoid([x, h_{t-1}] @ W + b) ----
        float s1[16];
        if (t > 0){
            ulonglong2 az[4], ar[4];
            #pragma unroll
            for (int i = 0; i < 4; i++){ az[i] = make_ulonglong2(0,0); ar[i] = make_ulonglong2(0,0); }

            float4 pf[2];
            #pragma unroll
            for (int u = 0; u < 2; u++) pf[u] = __ldcg((const float4*)hsrc1[u]);
            #pragma unroll 1
            for (int ch = 0; ch < NCH; ch++){
                float* buf = (ch & 1) ? hS1 : hS0;
                #pragma unroll
                for (int u = 0; u < 2; u++) *(float4*)(buf + sdst[u]) = pf[u];
                __syncthreads();
                if (ch < NCH-1){
                    int kc = (ch+1)*KC;
                    #pragma unroll
                    for (int u = 0; u < 2; u++) pf[u] = __ldcg((const float4*)(hsrc1[u] + kc));
                }
                const ulonglong2* wz = W4Zu + (ch*64 + kh*16)*16 + p;
                const ulonglong2* wr = W4Ru + (ch*64 + kh*16)*16 + p;
                const float* hb = buf + kh*32;
                #pragma unroll 4
                for (int it = 0; it < 8; it++){
                    ulonglong2 wz0 = wz[(2*it)*16],   wr0 = wr[(2*it)*16];
                    ulonglong2 wz1 = wz[(2*it+1)*16], wr1 = wr[(2*it+1)*16];
                    ulonglong2 hh0 = *(const ulonglong2*)(hb + (b0+0)*HSS + 4*it);
                    ulonglong2 hh1 = *(const ulonglong2*)(hb + (b0+1)*HSS + 4*it);
                    ulonglong2 hh2 = *(const ulonglong2*)(hb + (b0+2)*HSS + 4*it);
                    ulonglong2 hh3 = *(const ulonglong2*)(hb + (b0+3)*HSS + 4*it);
                    P1B(hh0, wz0, wz1, wr0, wr1, az[0], ar[0])
                    P1B(hh1, wz0, wz1, wr0, wr1, az[1], ar[1])
                    P1B(hh2, wz0, wz1, wr0, wr1, az[2], ar[2])
                    P1B(hh3, wz0, wz1, wr0, wr1, az[3], ar[3])
                }
            }
            __syncthreads();   // red region aliases both buffers
            if (kh){
                int base = (kh-1)*128 + r7;
                #pragma unroll
                for (int i = 0; i < 4; i++){
                    red[(2*i+0)*384 + base]   = hsum2(az[i].x);
                    red[(2*i+1)*384 + base]   = hsum2(az[i].y);
                    red[(8+2*i+0)*384 + base] = hsum2(ar[i].x);
                    red[(8+2*i+1)*384 + base] = hsum2(ar[i].y);
                }
            }
            __syncthreads();
            if (!kh){
                #pragma unroll
                for (int i = 0; i < 4; i++){
                    s1[2*i]     = hsum2(az[i].x); s1[2*i+1]   = hsum2(az[i].y);
                    s1[8+2*i]   = hsum2(ar[i].x); s1[8+2*i+1] = hsum2(ar[i].y);
                }
                #pragma unroll
                for (int j = 0; j < 16; j++)
                    s1[j] += red[j*384 + r7] + red[j*384 + 128 + r7] + red[j*384 + 256 + r7];
            }
        } else if (!kh){
            #pragma unroll
            for (int j = 0; j < 16; j++) s1[j] = 0.f;
        }

        // r + hr store first (what other CTAs need), then arrive; z after arrive
        if (!kh){
            const float2 vr0 = *(const float2*)(cs + 32 + jp);
            const float2 brf = *(const float2*)(cs + 192 + jp);
            #pragma unroll
            for (int i = 0; i < 4; i++){
                float r0 = sigm(s1[8+2*i]   + xb[i]*vr0.x + brf.x);
                float r1 = sigm(s1[8+2*i+1] + xb[i]*vr0.y + brf.y);
                *(float2*)&g_hr[(gbase+i)*H_ + cc] = make_float2(ho_[i].x*r0, ho_[i].y*r1);
            }
        }

        bar++; bar_arrive(cnt);

        if (!kh){
            const float2 vz0 = *(const float2*)(cs + jp);
            const float2 bzf = *(const float2*)(cs + 160 + jp);
            #pragma unroll
            for (int i = 0; i < 4; i++){
                float z0 = sigm(s1[2*i]   + xb[i]*vz0.x + bzf.x);
                float z1 = sigm(s1[2*i+1] + xb[i]*vz0.y + bzf.y);
                z_[i] = make_float2(z0, z1);
            }
        }

        bar_wait(cnt, bar*16);

        float4 kv4 = make_float4(0.f,0.f,0.f,0.f);
        if (!kh) kv4 = __ldcg((const float4*)&g_k[gbase]);

        // ---- phase 2: h_tilde = tanh([x, h*r, St*k, Mass] @ Wh + bh) ----
        float s2[8];
        {
            ulonglong2 ah[4];
            #pragma unroll
            for (int i = 0; i < 4; i++) ah[i] = make_ulonglong2(0,0);

            float4 pf[2];
            #pragma unroll
            for (int u = 0; u < 2; u++) pf[u] = __ldcg((const float4*)hsrc2[u]);
            #pragma unroll 1
            for (int ch = 0; ch < NCH; ch++){
                float* buf = (ch & 1) ? hS1 : hS0;
                #pragma unroll
                for (int u = 0; u < 2; u++) *(float4*)(buf + sdst[u]) = pf[u];
                __syncthreads();
                if (ch < NCH-1){
                    int kc = (ch+1)*KC;
                    #pragma unroll
                    for (int u = 0; u < 2; u++) pf[u] = __ldcg((const float4*)(hsrc2[u] + kc));
                }
                const ulonglong2* wh = W4Hu + (ch*64 + kh*16)*16 + p;
                const float* hb = buf + kh*32;
                #pragma unroll
                for (int it = 0; it < 8; it++){
                    ulonglong2 w0 = wh[(2*it)*16], w1 = wh[(2*it+1)*16];
                    ulonglong2 hh0 = *(const ulonglong2*)(hb + (b0+0)*HSS + 4*it);
                    ulonglong2 hh1 = *(const ulonglong2*)(hb + (b0+1)*HSS + 4*it);
                    ulonglong2 hh2 = *(const ulonglong2*)(hb + (b0+2)*HSS + 4*it);
                    ulonglong2 hh3 = *(const ulonglong2*)(hb + (b0+3)*HSS + 4*it);
                    P2B(hh0, w0, w1, ah[0])
                    P2B(hh1, w0, w1, ah[1])
                    P2B(hh2, w0, w1, ah[2])
                    P2B(hh3, w0, w1, ah[3])
                }
            }
            // last MAC chunk uses hS1; red writes below touch hS0 only for j<8? (j*384 spans both)
            __syncthreads();
            if (kh){
                int base = (kh-1)*128 + r7;
                #pragma unroll
                for (int i = 0; i < 4; i++){
                    red[(2*i+0)*384 + base] = hsum2(ah[i].x);
                    red[(2*i+1)*384 + base] = hsum2(ah[i].y);
                }
            }
            __syncthreads();
            if (!kh){
                #pragma unroll
                for (int i = 0; i < 4; i++){
                    s2[2*i]   = hsum2(ah[i].x);
                    s2[2*i+1] = hsum2(ah[i].y);
                }
                #pragma unroll
                for (int j = 0; j < 8; j++)
                    s2[j] += red[j*384 + r7] + red[j*384 + 128 + r7] + red[j*384 + 256 + r7];
            }
        }

        if (!kh){
            const float2 vh0  = *(const float2*)(cs + 64 + jp);
            const float2 v513 = *(const float2*)(cs + 96 + jp);
            const float2 v514 = *(const float2*)(cs + 128 + jp);
            const float2 bhf  = *(const float2*)(cs + 224 + jp);
            const float2 wkf  = *(const float2*)(cs + 256 + jp);
            const float kvA[4] = {kv4.x, kv4.y, kv4.z, kv4.w};
            float kp[4];
            #pragma unroll
            for (int i = 0; i < 4; i++){
                float st_i = cs[288 + b0 + i];
                float ms_i = cs[320 + b0 + i];
                float sk = st_i * kvA[i];
                float a0 = s2[2*i]   + xb[i]*vh0.x + sk*v513.x + ms_i*v514.x + bhf.x;
                float a1 = s2[2*i+1] + xb[i]*vh0.y + sk*v513.y + ms_i*v514.y + bhf.y;
                float t0 = tanh_(a0), t1 = tanh_(a1);
                float hn0 = (1.f - z_[i].x)*ho_[i].x + z_[i].x*t0;
                float hn1 = (1.f - z_[i].y)*ho_[i].y + z_[i].y*t1;
                float2 hn = make_float2(hn0, hn1);
                __stcs((float2*)outp[i], hn);                      // write-only stream
                outp[i] += H_;
                *(float2*)&g_hstate[(gbase+i)*H_ + cc] = hn;       // L2-hot state
                ho_[i] = hn;
                kp[i] = hn0*wkf.x + hn1*wkf.y;
            }
            #pragma unroll
            for (int off = 8; off; off >>= 1){
                kp[0] += __shfl_down_sync(0xffffffffu, kp[0], off, 16);
                kp[1] += __shfl_down_sync(0xffffffffu, kp[1], off, 16);
                kp[2] += __shfl_down_sync(0xffffffffu, kp[2], off, 16);
                kp[3] += __shfl_down_sync(0xffffffffu, kp[3], off, 16);
            }
            if (p == 0){
                *(float4*)&g_kpart[tileN*B_ + gbase] = make_float4(kp[0], kp[1], kp[2], kp[3]);
            }
        }

        bar++; bar_arrive(cnt);
        bar_wait(cnt, bar*16);
    }
}

extern "C" void kernel_launch(void* const* d_in, const int* in_sizes, int n_in,
                              void* d_out, int out_size) {
    (void)in_sizes; (void)n_in; (void)out_size;
    const float* inputs = (const float*)d_in[0];
    const float* St     = (const float*)d_in[1];
    const float* Mass   = (const float*)d_in[2];
    const float* Wz     = (const float*)d_in[3];
    const float* bz     = (const float*)d_in[4];
    const float* Wr     = (const float*)d_in[5];
    const float* br     = (const float*)d_in[6];
    const float* Wh     = (const float*)d_in[7];
    const float* bh     = (const float*)d_in[8];
    const float* Wk     = (const float*)d_in[9];
    const float* bk     = (const float*)d_in[10];
    float* out = (float*)d_out;

    cudaFuncSetAttribute(mcgru_kernel, cudaFuncAttributeMaxDynamicSharedMemorySize, SMEM_BYTES);

    init_kernel<<<1, 256>>>();
    mcgru_kernel<<<NCTA, NTHR, SMEM_BYTES>>>(inputs, St, Mass, Wz, bz, Wr, br,
                                             Wh, bh, Wk, bk, out);
}